// round 9
// baseline (speedup 1.0000x reference)
#include <cuda_runtime.h>
#include <cstdint>

// upfirdn2d, UP=1, DOWN=2, PAD=5, separable sym6 (12 taps), fp32.
// Producer/consumer warp specialization: warps 0-7 run the vertical 12-tap
// stride-2 pass from global into a double-buffered smem chunk (16 out rows);
// warps 8-15 run the horizontal pass from the previous chunk to gmem.
// DRAM stays busy during horizontal compute (no serialized phase tail).

#define IMG_H   256
#define IMG_W   256
#define OUT_H   128
#define OUT_W   128
#define CHUNK   16            // output rows per pipeline chunk
#define NCHUNK  8             // chunks per image (128 rows)
#define STRIDE  276           // floats; 276 % 32 = 20 -> low-conflict LDS
#define PADL    8             // left zero pad; data words [8, 264)
#define BUFW    (CHUNK * STRIDE)
#define NT      512

#define HR0  ( 0.015404109327027373f)
#define HR1  ( 0.0034907120842174702f)
#define HR2  (-0.11799011114819057f)
#define HR3  (-0.048311742585633f)
#define HR4  ( 0.4910559419267466f)
#define HR5  ( 0.787641141030194f)
#define HR6  ( 0.3379294217276218f)
#define HR7  (-0.07263752278646252f)
#define HR8  (-0.021060292512300564f)
#define HR9  ( 0.04472490177066578f)
#define HR10 ( 0.0017677118642428036f)
#define HR11 (-0.007800708325034148f)

__device__ __forceinline__ float tap12(const float* w) {
    float a;
    a = HR0 * w[0];
    a = fmaf(HR1,  w[1],  a);
    a = fmaf(HR2,  w[2],  a);
    a = fmaf(HR3,  w[3],  a);
    a = fmaf(HR4,  w[4],  a);
    a = fmaf(HR5,  w[5],  a);
    a = fmaf(HR6,  w[6],  a);
    a = fmaf(HR7,  w[7],  a);
    a = fmaf(HR8,  w[8],  a);
    a = fmaf(HR9,  w[9],  a);
    a = fmaf(HR10, w[10], a);
    a = fmaf(HR11, w[11], a);
    return a;
}

__device__ __forceinline__ float2 tap12v(const float2* w) {
    float2 a;
    a.x = HR0 * w[0].x;            a.y = HR0 * w[0].y;
    a.x = fmaf(HR1,  w[1].x, a.x); a.y = fmaf(HR1,  w[1].y, a.y);
    a.x = fmaf(HR2,  w[2].x, a.x); a.y = fmaf(HR2,  w[2].y, a.y);
    a.x = fmaf(HR3,  w[3].x, a.x); a.y = fmaf(HR3,  w[3].y, a.y);
    a.x = fmaf(HR4,  w[4].x, a.x); a.y = fmaf(HR4,  w[4].y, a.y);
    a.x = fmaf(HR5,  w[5].x, a.x); a.y = fmaf(HR5,  w[5].y, a.y);
    a.x = fmaf(HR6,  w[6].x, a.x); a.y = fmaf(HR6,  w[6].y, a.y);
    a.x = fmaf(HR7,  w[7].x, a.x); a.y = fmaf(HR7,  w[7].y, a.y);
    a.x = fmaf(HR8,  w[8].x, a.x); a.y = fmaf(HR8,  w[8].y, a.y);
    a.x = fmaf(HR9,  w[9].x, a.x); a.y = fmaf(HR9,  w[9].y, a.y);
    a.x = fmaf(HR10, w[10].x, a.x); a.y = fmaf(HR10, w[10].y, a.y);
    a.x = fmaf(HR11, w[11].x, a.x); a.y = fmaf(HR11, w[11].y, a.y);
    return a;
}

// Vertical pass: 8 output rows x 2 columns, all 26 row-loads front-batched.
template<bool CHECK>
__device__ __forceinline__ void vpass8(const float2* __restrict__ colp,
                                       float* __restrict__ sdst, int g0)
{
    float2 w[26];
    #pragma unroll
    for (int t = 0; t < 26; t++) {
        int g = g0 + t;
        if (CHECK && (unsigned)g >= (unsigned)IMG_H) w[t] = make_float2(0.f, 0.f);
        else                                         w[t] = __ldg(colp + g * (IMG_W / 2));
    }
    #pragma unroll
    for (int i = 0; i < 8; i++) {
        float2 o = tap12v(&w[2 * i]);
        *reinterpret_cast<float2*>(sdst + i * STRIDE) = o;
    }
}

__global__ void __launch_bounds__(NT, 2)
hp_sym6_v7(const float* __restrict__ in, float* __restrict__ out)
{
    extern __shared__ float sbuf[];   // [2][CHUNK][STRIDE]

    const int img = blockIdx.x;
    const int tid = threadIdx.x;

    const float* __restrict__ src    = in  + (size_t)img * (IMG_H * IMG_W);
    float*       __restrict__ dstimg = out + (size_t)img * (OUT_H * OUT_W);

    // zero pad columns of both buffers: words [0,8) and [264,276) per row
    #pragma unroll
    for (int z = tid; z < 2 * CHUNK * 20; z += NT) {
        int b  = z / (CHUNK * 20);
        int zz = z - b * (CHUNK * 20);
        int rr = zz / 20;
        int pz = zz - rr * 20;
        sbuf[b * BUFW + rr * STRIDE + (pz < 8 ? pz : 256 + pz)] = 0.0f;
    }
    __syncthreads();

    const bool producer = (tid < 256);

    // producer mapping: strip h covers chunk rows h*8..h*8+7; 2 cols/thread
    const int h   = (tid >> 7) & 1;
    const int c2  = (tid & 127) * 2;
    const float2* colp = reinterpret_cast<const float2*>(src + c2);

    // consumer mapping: row within chunk + group of 8 output cols
    const int ctid = tid & 255;
    const int crow = ctid & 15;         // 0..15
    const int cg   = ctid >> 4;         // 0..15 -> cols 8*cg .. 8*cg+7

    for (int t = 0; t <= NCHUNK; t++) {
        if (producer) {
            if (t < NCHUNK) {
                float* buf  = sbuf + (t & 1) * BUFW;
                float* sdst = buf + (h * 8) * STRIDE + PADL + c2;
                const int g0 = 2 * (t * CHUNK + h * 8) - 5;   // 26 rows needed
                if (g0 >= 0 && g0 + 25 < IMG_H) vpass8<false>(colp, sdst, g0);
                else                            vpass8<true >(colp, sdst, g0);
            }
        } else {
            if (t > 0) {
                const float* buf  = sbuf + ((t - 1) & 1) * BUFW;
                const float* rowv = buf + crow * STRIDE + 16 * cg;

                float v[32];
                #pragma unroll
                for (int m = 0; m < 8; m++) {
                    float4 q = *reinterpret_cast<const float4*>(rowv + 4 * m);
                    v[4 * m + 0] = q.x;
                    v[4 * m + 1] = q.y;
                    v[4 * m + 2] = q.z;
                    v[4 * m + 3] = q.w;
                }

                float o[8];
                #pragma unroll
                for (int d = 0; d < 8; d++)
                    o[d] = tap12(&v[2 * d + 3]);

                float* dst = dstimg + ((t - 1) * CHUNK + crow) * OUT_W + 8 * cg;
                *reinterpret_cast<float4*>(dst)     = make_float4(o[0], o[1], o[2], o[3]);
                *reinterpret_cast<float4*>(dst + 4) = make_float4(o[4], o[5], o[6], o[7]);
            }
        }
        __syncthreads();
    }
}

extern "C" void kernel_launch(void* const* d_in, const int* in_sizes, int n_in,
                              void* d_out, int out_size)
{
    const float* x = (const float*)d_in[0];
    float* y = (float*)d_out;

    int n_img = in_sizes[0] / (IMG_H * IMG_W);        // 1024
    size_t smem = (size_t)2 * BUFW * sizeof(float);   // 35328 B

    cudaFuncSetAttribute(hp_sym6_v7,
                         cudaFuncAttributeMaxDynamicSharedMemorySize, (int)smem);

    hp_sym6_v7<<<n_img, NT, smem>>>(x, y);
}

// round 10
// speedup vs baseline: 1.0401x; 1.0401x over previous
#include <cuda_runtime.h>
#include <cstdint>

// upfirdn2d, UP=1, DOWN=2, PAD=5, separable sym6 (12 taps), fp32.
// cp.async-pipelined: 64-row smem input ring (4 x 16-row slots) filled by
// LDGSTS with depth-2 chunk lookahead; per 8-output-row chunk, vertical
// 12-tap from the ring -> smem tmp -> horizontal 12-tap -> gmem.
// No register load-ring => 42 regs => 3 CTAs/SM (48 warps) with high MLP.

#define IMG_H   256
#define IMG_W   256
#define OUT_H   128
#define OUT_W   128
#define NT      512
#define NCH     8             // compute chunks per CTA (8 out rows each)
#define NLOAD   9             // load chunks per CTA (16 input rows each)
#define RSTRIDE 256           // ring row stride (floats)
#define TSTRIDE 276           // tmp row stride; 276 % 32 = 20
#define PADL    8

#define HR0  ( 0.015404109327027373f)
#define HR1  ( 0.0034907120842174702f)
#define HR2  (-0.11799011114819057f)
#define HR3  (-0.048311742585633f)
#define HR4  ( 0.4910559419267466f)
#define HR5  ( 0.787641141030194f)
#define HR6  ( 0.3379294217276218f)
#define HR7  (-0.07263752278646252f)
#define HR8  (-0.021060292512300564f)
#define HR9  ( 0.04472490177066578f)
#define HR10 ( 0.0017677118642428036f)
#define HR11 (-0.007800708325034148f)

__device__ __forceinline__ float tap12(const float* w) {
    float a;
    a = HR0 * w[0];
    a = fmaf(HR1,  w[1],  a);
    a = fmaf(HR2,  w[2],  a);
    a = fmaf(HR3,  w[3],  a);
    a = fmaf(HR4,  w[4],  a);
    a = fmaf(HR5,  w[5],  a);
    a = fmaf(HR6,  w[6],  a);
    a = fmaf(HR7,  w[7],  a);
    a = fmaf(HR8,  w[8],  a);
    a = fmaf(HR9,  w[9],  a);
    a = fmaf(HR10, w[10], a);
    a = fmaf(HR11, w[11], a);
    return a;
}

__device__ __forceinline__ void cp_async16(uint32_t saddr, const void* gptr) {
    asm volatile("cp.async.cg.shared.global [%0], [%1], 16;\n"
                 :: "r"(saddr), "l"(gptr));
}
__device__ __forceinline__ void cp_commit() {
    asm volatile("cp.async.commit_group;\n" ::: "memory");
}
template<int N>
__device__ __forceinline__ void cp_wait() {
    asm volatile("cp.async.wait_group %0;\n" :: "n"(N) : "memory");
}

__global__ void __launch_bounds__(NT, 3)
hp_sym6_v8(const float* __restrict__ in, float* __restrict__ out)
{
    // smem: input ring [64][256] (65536 B) + tmp [8][276] (8832 B)
    extern __shared__ float smem_[];
    float* s_ring = smem_;                 // 64 * 256
    float* s_tmp  = smem_ + 64 * RSTRIDE;  // 8 * 276

    const int ty  = blockIdx.x;            // image half (0..1)
    const int img = blockIdx.y;
    const int tid = threadIdx.x;
    const int i0  = ty * 64;               // first output row
    const int g0  = 2 * i0 - 5;            // first input row needed

    const float* __restrict__ src    = in  + (size_t)img * (IMG_H * IMG_W);
    float*       __restrict__ dstimg = out + (size_t)img * (OUT_H * OUT_W);

    // zero tmp pad words [0,8) and [264,276) per row (persist; V never writes them)
    for (int z = tid; z < 8 * 20; z += NT) {
        int rr = z / 20;
        int pz = z - rr * 20;
        s_tmp[rr * TSTRIDE + (pz < 8 ? pz : 256 + pz)] = 0.0f;
    }

    // load-chunk issue: 16 rows x 256 floats; thread -> (row = tid>>5, 2 quads)
    const int lrow = tid >> 5;             // 0..15
    const int lq   = (tid & 31) * 2;       // float4 index 0..62

    auto issue_load = [&](int L) {
        if (L < NLOAD) {
            int rel = 16 * L + lrow;
            int g   = g0 + rel;
            uint32_t sa = (uint32_t)__cvta_generic_to_shared(
                s_ring + (rel & 63) * RSTRIDE + lq * 4);
            if ((unsigned)g < (unsigned)IMG_H) {
                const float4* gp = reinterpret_cast<const float4*>(src + g * IMG_W) + lq;
                cp_async16(sa, gp);
                cp_async16(sa + 16, gp + 1);
            } else {
                float4 z4 = make_float4(0.f, 0.f, 0.f, 0.f);
                *reinterpret_cast<float4*>(s_ring + (rel & 63) * RSTRIDE + lq * 4)     = z4;
                *reinterpret_cast<float4*>(s_ring + (rel & 63) * RSTRIDE + lq * 4 + 4) = z4;
            }
        }
        cp_commit();   // uniform group count even when empty
    };

    // prologue: chunks 0,1,2 in flight
    issue_load(0);
    issue_load(1);
    issue_load(2);

    // V mapping: (col, half): half h -> 4 out rows, 18-row input window
    const int vcol = tid & 255;
    const int vh   = tid >> 8;
    // H mapping: (orow, out col pair)
    const int orow = tid >> 6;             // 0..7
    const int ocp  = tid & 63;             // outputs 2*ocp, 2*ocp+1

    for (int c = 0; c < NCH; c++) {
        issue_load(c + 3);
        cp_wait<2>();          // load-chunks <= c+1 complete
        __syncthreads();       // ring visible; prev H done before tmp overwrite

        // ---- vertical: out rows 8c+4vh .. +3 ; input rel rows 16c+8vh .. +17 ----
        {
            const int base = 16 * c + 8 * vh;
            float w[18];
            #pragma unroll
            for (int k = 0; k < 18; k++)
                w[k] = s_ring[((base + k) & 63) * RSTRIDE + vcol];
            #pragma unroll
            for (int m = 0; m < 4; m++)
                s_tmp[(4 * vh + m) * TSTRIDE + PADL + vcol] = tap12(&w[2 * m]);
        }
        __syncthreads();

        // ---- horizontal: 2 outputs per thread from tmp row orow ----
        {
            const float* rowv = s_tmp + orow * TSTRIDE + 4 * ocp;
            float v[20];
            #pragma unroll
            for (int m = 0; m < 5; m++) {
                float4 q = *reinterpret_cast<const float4*>(rowv + 4 * m);
                v[4 * m + 0] = q.x;
                v[4 * m + 1] = q.y;
                v[4 * m + 2] = q.z;
                v[4 * m + 3] = q.w;
            }
            float2 o;
            o.x = tap12(&v[3]);
            o.y = tap12(&v[5]);
            *reinterpret_cast<float2*>(
                dstimg + (i0 + 8 * c + orow) * OUT_W + 2 * ocp) = o;
        }
        // no barrier here: next iteration's post-wait barrier orders
        // H-reads (this chunk) before V-writes (next chunk).
    }
}

extern "C" void kernel_launch(void* const* d_in, const int* in_sizes, int n_in,
                              void* d_out, int out_size)
{
    const float* x = (const float*)d_in[0];
    float* y = (float*)d_out;

    int n_img = in_sizes[0] / (IMG_H * IMG_W);                    // 1024
    size_t smem = (size_t)(64 * RSTRIDE + 8 * TSTRIDE) * sizeof(float); // 74368 B

    cudaFuncSetAttribute(hp_sym6_v8,
                         cudaFuncAttributeMaxDynamicSharedMemorySize, (int)smem);

    dim3 grid(OUT_H / 64, n_img);   // (2, 1024)
    hp_sym6_v8<<<grid, NT, smem>>>(x, y);
}

// round 13
// speedup vs baseline: 1.0424x; 1.0022x over previous
#include <cuda_runtime.h>
#include <cstdint>

// upfirdn2d, UP=1, DOWN=2, PAD=5, separable sym6 (12 taps), fp32.
// cp.async pipeline + intra-CTA warp specialization:
//   all threads: issue 8-row cp.async load chunks into a 48-row smem ring
//   warps 0-7:  vertical 12-tap stride-2 (chunk c)  ring -> tmp[c&1]
//   warps 8-15: horizontal 12-tap stride-2 (chunk c-1) tmp -> gmem
// FIXES vs v10: chunk c depends on load chunks 2c..2c+3 (rel rows 16c..16c+25)
//   -> cp_wait<2> (not <3>), and NLC=18 (rel rows up to 143 >= 137 needed).

#define IMG_H   256
#define IMG_W   256
#define OUT_H   128
#define OUT_W   128
#define NT      512
#define NCH     8             // compute chunks per CTA (8 out rows each)
#define NLC     18            // 8-input-row load chunks (144 rows >= 138 needed)
#define RROWS   48            // ring rows (6 slots x 8)
#define RSTRIDE 256
#define TSTRIDE 276           // 276 % 32 = 20; row base 1104 B = 16B-aligned
#define PADL    8
#define TBUF    (8 * TSTRIDE)

#define HR0  ( 0.015404109327027373f)
#define HR1  ( 0.0034907120842174702f)
#define HR2  (-0.11799011114819057f)
#define HR3  (-0.048311742585633f)
#define HR4  ( 0.4910559419267466f)
#define HR5  ( 0.787641141030194f)
#define HR6  ( 0.3379294217276218f)
#define HR7  (-0.07263752278646252f)
#define HR8  (-0.021060292512300564f)
#define HR9  ( 0.04472490177066578f)
#define HR10 ( 0.0017677118642428036f)
#define HR11 (-0.007800708325034148f)

__device__ __forceinline__ float tap12(const float* w) {
    float a;
    a = HR0 * w[0];
    a = fmaf(HR1,  w[1],  a);
    a = fmaf(HR2,  w[2],  a);
    a = fmaf(HR3,  w[3],  a);
    a = fmaf(HR4,  w[4],  a);
    a = fmaf(HR5,  w[5],  a);
    a = fmaf(HR6,  w[6],  a);
    a = fmaf(HR7,  w[7],  a);
    a = fmaf(HR8,  w[8],  a);
    a = fmaf(HR9,  w[9],  a);
    a = fmaf(HR10, w[10], a);
    a = fmaf(HR11, w[11], a);
    return a;
}

__device__ __forceinline__ void cp_async16(uint32_t saddr, const void* gptr) {
    asm volatile("cp.async.cg.shared.global [%0], [%1], 16;\n"
                 :: "r"(saddr), "l"(gptr));
}
__device__ __forceinline__ void cp_commit() {
    asm volatile("cp.async.commit_group;\n" ::: "memory");
}
template<int N>
__device__ __forceinline__ void cp_wait() {
    asm volatile("cp.async.wait_group %0;\n" :: "n"(N) : "memory");
}

// H for one chunk row: 4 outputs from a 24-word smem window.
__device__ __forceinline__ void hquad(const float* __restrict__ rowv,
                                      float* __restrict__ dst)
{
    float v[24];
    #pragma unroll
    for (int m = 0; m < 6; m++) {
        float4 q = *reinterpret_cast<const float4*>(rowv + 4 * m);
        v[4 * m + 0] = q.x;
        v[4 * m + 1] = q.y;
        v[4 * m + 2] = q.z;
        v[4 * m + 3] = q.w;
    }
    float4 o;
    o.x = tap12(&v[3]);
    o.y = tap12(&v[5]);
    o.z = tap12(&v[7]);
    o.w = tap12(&v[9]);
    *reinterpret_cast<float4*>(dst) = o;
}

__global__ void __launch_bounds__(NT, 3)
hp_sym6_v11(const float* __restrict__ in, float* __restrict__ out)
{
    extern __shared__ float smem_[];
    float* s_ring = smem_;                        // 48 * 256  (49152 B)
    float* s_tmp  = smem_ + RROWS * RSTRIDE;      // 2 * 8 * 276 (17664 B)

    const int ty  = blockIdx.x;                   // image half
    const int img = blockIdx.y;
    const int tid = threadIdx.x;
    const int i0  = ty * 64;
    const int g0  = 2 * i0 - 5;

    const float* __restrict__ src    = in  + (size_t)img * (IMG_H * IMG_W);
    float*       __restrict__ dstimg = out + (size_t)img * (OUT_H * OUT_W);

    // zero tmp pad words [0,8) and [264,276) of both buffers
    for (int z = tid; z < 2 * 8 * 20; z += NT) {
        int b  = z / 160;
        int zz = z - b * 160;
        int rr = zz / 20;
        int pz = zz - rr * 20;
        s_tmp[b * TBUF + rr * TSTRIDE + (pz < 8 ? pz : 256 + pz)] = 0.0f;
    }

    // load chunk L = 8 input rows; 1 cp.async16 per thread
    const int lrow = tid >> 6;                    // 0..7
    const int lq   = tid & 63;                    // float4 index

    auto issue_load = [&](int L) {
        if (L < NLC) {
            int rel  = 8 * L + lrow;
            int srow = (L % 6) * 8 + lrow;        // ring slot row
            float* sp = s_ring + srow * RSTRIDE + lq * 4;
            int g = g0 + rel;
            if ((unsigned)g < (unsigned)IMG_H) {
                cp_async16((uint32_t)__cvta_generic_to_shared(sp),
                           reinterpret_cast<const float4*>(src + g * IMG_W) + lq);
            } else {
                *reinterpret_cast<float4*>(sp) = make_float4(0.f, 0.f, 0.f, 0.f);
            }
        }
        cp_commit();
    };

    issue_load(0); issue_load(1); issue_load(2);
    issue_load(3); issue_load(4); issue_load(5);

    const bool vhalf = (tid < 256);
    // V mapping: one column, 8 outputs (26-row window), smem register ring
    const int vcol = tid & 255;
    // H mapping: (row in chunk, group of 4 outputs)
    const int hrow = (tid & 255) >> 5;            // 0..7
    const int hgrp = tid & 31;                    // 0..31 -> cols 4*hgrp..+3

    for (int c = 0; c < NCH; c++) {
        cp_wait<2>();          // load chunks <= 2c+3 complete (chunk c needs 2c..2c+3)
        __syncthreads();       // ring visible; prev-chunk H reads done

        if (vhalf) {
            // input rel rows 16c .. 16c+25 ; ring row = (16c mod 48) + k wrap
            const int rbase = (c % 3) * 16;
            float* tdst = s_tmp + (c & 1) * TBUF + PADL + vcol;

            float w[12];
            #pragma unroll
            for (int t = 0; t < 10; t++) {
                int r = rbase + t;  if (r >= RROWS) r -= RROWS;
                w[t] = s_ring[r * RSTRIDE + vcol];
            }
            #pragma unroll
            for (int m = 0; m < 8; m++) {
                int rA = rbase + 2 * m + 10; if (rA >= RROWS) rA -= RROWS;
                int rB = rbase + 2 * m + 11; if (rB >= RROWS) rB -= RROWS;
                w[10] = s_ring[rA * RSTRIDE + vcol];
                w[11] = s_ring[rB * RSTRIDE + vcol];
                tdst[m * TSTRIDE] = tap12(w);
                #pragma unroll
                for (int k = 0; k < 10; k++) w[k] = w[k + 2];
            }
        } else if (c > 0) {
            const float* rowv = s_tmp + ((c - 1) & 1) * TBUF
                              + hrow * TSTRIDE + 8 * hgrp;
            hquad(rowv, dstimg + (i0 + 8 * (c - 1) + hrow) * OUT_W + 4 * hgrp);
        }
        __syncthreads();
        issue_load(2 * c + 6);
        issue_load(2 * c + 7);
    }

    // final H for chunk NCH-1 (tmp[1] written at c=7, ordered by last barrier)
    if (!vhalf) {
        const float* rowv = s_tmp + ((NCH - 1) & 1) * TBUF
                          + hrow * TSTRIDE + 8 * hgrp;
        hquad(rowv, dstimg + (i0 + 8 * (NCH - 1) + hrow) * OUT_W + 4 * hgrp);
    }
}

extern "C" void kernel_launch(void* const* d_in, const int* in_sizes, int n_in,
                              void* d_out, int out_size)
{
    const float* x = (const float*)d_in[0];
    float* y = (float*)d_out;

    int n_img = in_sizes[0] / (IMG_H * IMG_W);                        // 1024
    size_t smem = (size_t)(RROWS * RSTRIDE + 2 * TBUF) * sizeof(float); // 66816 B

    cudaFuncSetAttribute(hp_sym6_v11,
                         cudaFuncAttributeMaxDynamicSharedMemorySize, (int)smem);

    dim3 grid(OUT_H / 64, n_img);   // (2, 1024)
    hp_sym6_v11<<<grid, NT, smem>>>(x, y);
}